// round 7
// baseline (speedup 1.0000x reference)
#include <cuda_runtime.h>

// LMorph: out[n,o,h,w] = sum_{c,ij} t^(p+1) / sum_{c,ij} t^p,
//   t = (1 + (in - gmin)/(gmax - gmin))[n,c,h+i,w+j] + filt[o,c,i,j]
// Shapes: in [4,2,256,256] f32, filt [4,2,5,5] f32, p [4,2] f32, out [4,4,252,252] f32.
// Each thread computes EIGHT outputs: rows (oh+{0,8,16,24}) x cols (ow, ow+32), packed f32x2.
// Grid = 512 CTAs = exactly one wave at 4 CTAs/SM on 148 SMs.

#define N_  4
#define C_  2
#define O_  4
#define H_  256
#define W_  256
#define KH_ 5
#define KW_ 5
#define K2_ (KH_ * KW_)
#define HO_ 252
#define WO_ 252

#define TX 32
#define TY 8
#define NT (TX * TY)
#define OWB 64              // output columns per block (2 per thread)
#define OHB 32              // output rows per block (4 per thread: ty+8k)
#define SWP 36              // pair-columns in tile
#define SH2 (OHB + KH_ - 1) // 36 tile rows

#define MMB 128             // minmax partial blocks

typedef unsigned long long u64t;

__device__ __forceinline__ float fast_lg2(float x) {
    float r;
    asm("lg2.approx.f32 %0, %1;" : "=f"(r) : "f"(x));
    return r;
}
__device__ __forceinline__ u64t pack2(float a, float b) {
    u64t r; asm("mov.b64 %0, {%1, %2};" : "=l"(r) : "f"(a), "f"(b)); return r;
}
__device__ __forceinline__ float2 unpack2(u64t v) {
    float2 f; asm("mov.b64 {%0, %1}, %2;" : "=f"(f.x), "=f"(f.y) : "l"(v)); return f;
}
__device__ __forceinline__ u64t fma2_(u64t a, u64t b, u64t c) {
    u64t r; asm("fma.rn.f32x2 %0, %1, %2, %3;" : "=l"(r) : "l"(a), "l"(b), "l"(c)); return r;
}
__device__ __forceinline__ u64t add2_(u64t a, u64t b) {
    u64t r; asm("add.rn.f32x2 %0, %1, %2;" : "=l"(r) : "l"(a), "l"(b)); return r;
}

// ---- orderable-uint encoding for float min/max ----
__device__ __forceinline__ unsigned f2key(float f) {
    unsigned u = __float_as_uint(f);
    return (u & 0x80000000u) ? ~u : (u | 0x80000000u);
}
__device__ __forceinline__ float key2f(unsigned k) {
    unsigned u = (k & 0x80000000u) ? (k & 0x7FFFFFFFu) : ~k;
    return __uint_as_float(u);
}

// per-block partial min/max keys (no atomics, no init kernel)
__device__ unsigned g_plo[MMB];
__device__ unsigned g_phi[MMB];

__global__ __launch_bounds__(256) void lmorph_minmax_kernel(
    const float* __restrict__ in, int n4)
{
    __shared__ unsigned slo[8], shi[8];
    unsigned lo = 0xFFFFFFFFu, hi = 0u;
    const float4* in4 = (const float4*)in;
    for (int i = blockIdx.x * blockDim.x + threadIdx.x; i < n4;
         i += gridDim.x * blockDim.x) {
        float4 v = in4[i];
        unsigned kx = f2key(v.x), ky = f2key(v.y), kz = f2key(v.z), kw = f2key(v.w);
        hi = max(hi, max(max(kx, ky), max(kz, kw)));
        lo = min(lo, min(min(kx, ky), min(kz, kw)));
    }
#pragma unroll
    for (int s = 16; s > 0; s >>= 1) {
        hi = max(hi, __shfl_xor_sync(0xFFFFFFFFu, hi, s));
        lo = min(lo, __shfl_xor_sync(0xFFFFFFFFu, lo, s));
    }
    int wid = threadIdx.x >> 5;
    if ((threadIdx.x & 31) == 0) { slo[wid] = lo; shi[wid] = hi; }
    __syncthreads();
    if (threadIdx.x == 0) {
        lo = slo[0]; hi = shi[0];
#pragma unroll
        for (int i = 1; i < 8; i++) { lo = min(lo, slo[i]); hi = max(hi, shi[i]); }
        g_plo[blockIdx.x] = lo;
        g_phi[blockIdx.x] = hi;
    }
}

__global__ __launch_bounds__(NT) void lmorph_main_kernel(
    const float* __restrict__ in,
    const float* __restrict__ filt,
    const float* __restrict__ p,
    float* __restrict__ out)
{
    __shared__ u64t sx[C_][SH2][SWP];  // packed raw pairs (x[w], x[w+32])
    __shared__ u64t sf2[C_][K2_];      // packed broadcast: 1 + f - lo*inv
    __shared__ float sscal[2];         // lo, inv

    const int z = blockIdx.z;          // n*O_ + o
    const int n = z >> 2;
    const int o = z & 3;
    const int w0 = blockIdx.x * OWB;
    const int h0 = blockIdx.y * OHB;
    const int tid = threadIdx.x;
    const int tx = tid & 31;
    const int ty = tid >> 5;

    // Phase A: raw packed tile load (clamped cols/rows are safe fillers)
    for (int idx = tid; idx < C_ * SH2 * SWP; idx += NT) {
        int c   = idx / (SH2 * SWP);
        int rem = idx - c * (SH2 * SWP);
        int r   = rem / SWP;
        int q   = rem - r * SWP;
        int h  = min(h0 + r, H_ - 1);
        int wA = min(w0 + q, W_ - 1);
        int wB = min(w0 + q + 32, W_ - 1);
        const float* row = in + ((n * C_ + c) * H_ + h) * W_;
        sx[c][r][q] = pack2(row[wA], row[wB]);
    }

    // Phase B: warp 0 reduces the 128 min/max partials
    if (tid < 32) {
        unsigned lo = 0xFFFFFFFFu, hi = 0u;
#pragma unroll
        for (int i = 0; i < MMB / 32; i++) {
            lo = min(lo, g_plo[tid + 32 * i]);
            hi = max(hi, g_phi[tid + 32 * i]);
        }
#pragma unroll
        for (int s = 16; s > 0; s >>= 1) {
            lo = min(lo, __shfl_xor_sync(0xFFFFFFFFu, lo, s));
            hi = max(hi, __shfl_xor_sync(0xFFFFFFFFu, hi, s));
        }
        if (tid == 0) {
            float flo = key2f(lo), fhi = key2f(hi);
            sscal[0] = flo;
            sscal[1] = __fdividef(1.0f, fhi - flo);
        }
    }
    __syncthreads();

    const float lo  = sscal[0];
    const float inv = sscal[1];

    // Phase C: folded filters, packed broadcast: t = x*inv + (1 + f - lo*inv)
    if (tid < C_ * K2_) {
        int c = tid / K2_;
        int k = tid - c * K2_;
        float v = 1.0f + filt[(o * C_ + c) * K2_ + k] - lo * inv;
        sf2[c][k] = pack2(v, v);
    }

    // per-channel packed poly coeffs for 2^(pe*l), degree 4: Ck = Ak * pe^k
    const float A1 = 0.69314718f, A2 = 0.24022651f, A3 = 0.05550411f,
                A4 = 0.00961813f;
    u64t K1[C_], K2p[C_], K3[C_], K4[C_];
#pragma unroll
    for (int c = 0; c < C_; c++) {
        float pe  = p[o * C_ + c];
        float pe2 = pe * pe;
        float c1 = A1 * pe, c2 = A2 * pe2, c3 = A3 * pe2 * pe, c4 = A4 * pe2 * pe2;
        K1[c] = pack2(c1, c1); K2p[c] = pack2(c2, c2);
        K3[c] = pack2(c3, c3); K4[c]  = pack2(c4, c4);
    }
    __syncthreads();

    const int ow  = w0 + tx;
    const int ow2 = ow + 32;

    const u64t inv2 = pack2(inv, inv);
    const u64t ONE2 = pack2(1.0f, 1.0f);

    u64t num[4], den[4];
#pragma unroll
    for (int r = 0; r < 4; r++) { num[r] = 0ull; den[r] = 0ull; }

#pragma unroll
    for (int c = 0; c < C_; c++) {
        const u64t k1 = K1[c], k2 = K2p[c], k3 = K3[c], k4 = K4[c];
#pragma unroll
        for (int i = 0; i < KH_; i++) {
#pragma unroll
            for (int j = 0; j < KW_; j++) {
                const int k = i * KW_ + j;
                const u64t f2k = sf2[c][k];
                u64t t0 = fma2_(sx[c][ty      + i][tx + j], inv2, f2k);
                u64t t1 = fma2_(sx[c][ty + 8  + i][tx + j], inv2, f2k);
                u64t t2 = fma2_(sx[c][ty + 16 + i][tx + j], inv2, f2k);
                u64t t3 = fma2_(sx[c][ty + 24 + i][tx + j], inv2, f2k);
                float2 f0 = unpack2(t0), f1 = unpack2(t1);
                float2 f2 = unpack2(t2), f3 = unpack2(t3);
                u64t l0 = pack2(fast_lg2(f0.x), fast_lg2(f0.y));
                u64t l1 = pack2(fast_lg2(f1.x), fast_lg2(f1.y));
                u64t l2 = pack2(fast_lg2(f2.x), fast_lg2(f2.y));
                u64t l3 = pack2(fast_lg2(f3.x), fast_lg2(f3.y));
                u64t u0 = fma2_(l0, k4, k3);
                u64t u1 = fma2_(l1, k4, k3);
                u64t u2 = fma2_(l2, k4, k3);
                u64t u3 = fma2_(l3, k4, k3);
                u0 = fma2_(l0, u0, k2);  u1 = fma2_(l1, u1, k2);
                u2 = fma2_(l2, u2, k2);  u3 = fma2_(l3, u3, k2);
                u0 = fma2_(l0, u0, k1);  u1 = fma2_(l1, u1, k1);
                u2 = fma2_(l2, u2, k1);  u3 = fma2_(l3, u3, k1);
                u64t w0p = fma2_(l0, u0, ONE2);
                u64t w1p = fma2_(l1, u1, ONE2);
                u64t w2p = fma2_(l2, u2, ONE2);
                u64t w3p = fma2_(l3, u3, ONE2);
                den[0] = add2_(den[0], w0p);  num[0] = fma2_(w0p, t0, num[0]);
                den[1] = add2_(den[1], w1p);  num[1] = fma2_(w1p, t1, num[1]);
                den[2] = add2_(den[2], w2p);  num[2] = fma2_(w2p, t2, num[2]);
                den[3] = add2_(den[3], w3p);  num[3] = fma2_(w3p, t3, num[3]);
            }
        }
    }

    float* obase = out + (n * O_ + o) * HO_ * WO_;
#pragma unroll
    for (int r = 0; r < 4; r++) {
        int oh = h0 + ty + 8 * r;
        if (oh < HO_) {
            float2 nf = unpack2(num[r]);
            float2 df = unpack2(den[r]);
            float* orow = obase + oh * WO_;
            orow[ow] = __fdividef(nf.x, df.x);
            if (ow2 < WO_) orow[ow2] = __fdividef(nf.y, df.y);
        }
    }
}

extern "C" void kernel_launch(void* const* d_in, const int* in_sizes, int n_in,
                              void* d_out, int out_size) {
    const float* in   = (const float*)d_in[0];   // [4,2,256,256]
    const float* filt = (const float*)d_in[1];   // [4,2,5,5]
    const float* p    = (const float*)d_in[2];   // [4,2]
    float* out = (float*)d_out;                  // [4,4,252,252]

    lmorph_minmax_kernel<<<MMB, 256>>>(in, (N_ * C_ * H_ * W_) / 4);

    dim3 block(NT);
    dim3 grid((WO_ + OWB - 1) / OWB, (HO_ + OHB - 1) / OHB, N_ * O_);
    lmorph_main_kernel<<<grid, block>>>(in, filt, p, out);
}

// round 8
// speedup vs baseline: 1.1031x; 1.1031x over previous
#include <cuda_runtime.h>

// LMorph: out[n,o,h,w] = sum_{c,ij} t^(p+1) / sum_{c,ij} t^p,
//   t = (1 + (in - gmin)/(gmax - gmin))[n,c,h+i,w+j] + filt[o,c,i,j]
// Shapes: in [4,2,256,256] f32, filt [4,2,5,5] f32, p [4,2] f32, out [4,4,252,252] f32.
// Block = 128 threads (4 warps). Each thread: 8 outputs = rows ty+{0,4,8,12} x cols (ow, ow+32),
// packed f32x2. Grid = 1024 CTAs x 4 warps = 4096 warps -> single wave on 148 SMs.

#define N_  4
#define C_  2
#define O_  4
#define H_  256
#define W_  256
#define KH_ 5
#define KW_ 5
#define K2_ (KH_ * KW_)
#define HO_ 252
#define WO_ 252

#define TX 32
#define TYW 4               // warps per block
#define NT (TX * TYW)       // 128 threads
#define OWB 64              // output columns per block (2 per thread)
#define OHB 16              // output rows per block (4 per thread: ty+4k)
#define SWP 36              // pair-columns in tile
#define SH2 (OHB + KH_ - 1) // 20 tile rows

#define MMB 128             // minmax partial blocks

typedef unsigned long long u64t;

__device__ __forceinline__ float fast_lg2(float x) {
    float r;
    asm("lg2.approx.f32 %0, %1;" : "=f"(r) : "f"(x));
    return r;
}
__device__ __forceinline__ u64t pack2(float a, float b) {
    u64t r; asm("mov.b64 %0, {%1, %2};" : "=l"(r) : "f"(a), "f"(b)); return r;
}
__device__ __forceinline__ float2 unpack2(u64t v) {
    float2 f; asm("mov.b64 {%0, %1}, %2;" : "=f"(f.x), "=f"(f.y) : "l"(v)); return f;
}
__device__ __forceinline__ u64t fma2_(u64t a, u64t b, u64t c) {
    u64t r; asm("fma.rn.f32x2 %0, %1, %2, %3;" : "=l"(r) : "l"(a), "l"(b), "l"(c)); return r;
}
__device__ __forceinline__ u64t add2_(u64t a, u64t b) {
    u64t r; asm("add.rn.f32x2 %0, %1, %2;" : "=l"(r) : "l"(a), "l"(b)); return r;
}

// ---- orderable-uint encoding for float min/max ----
__device__ __forceinline__ unsigned f2key(float f) {
    unsigned u = __float_as_uint(f);
    return (u & 0x80000000u) ? ~u : (u | 0x80000000u);
}
__device__ __forceinline__ float key2f(unsigned k) {
    unsigned u = (k & 0x80000000u) ? (k & 0x7FFFFFFFu) : ~k;
    return __uint_as_float(u);
}

// per-block partial min/max keys (no atomics, no init kernel)
__device__ unsigned g_plo[MMB];
__device__ unsigned g_phi[MMB];

__global__ __launch_bounds__(256) void lmorph_minmax_kernel(
    const float* __restrict__ in, int n4)
{
    __shared__ unsigned slo[8], shi[8];
    unsigned lo = 0xFFFFFFFFu, hi = 0u;
    const float4* in4 = (const float4*)in;
    for (int i = blockIdx.x * blockDim.x + threadIdx.x; i < n4;
         i += gridDim.x * blockDim.x) {
        float4 v = in4[i];
        unsigned kx = f2key(v.x), ky = f2key(v.y), kz = f2key(v.z), kw = f2key(v.w);
        hi = max(hi, max(max(kx, ky), max(kz, kw)));
        lo = min(lo, min(min(kx, ky), min(kz, kw)));
    }
#pragma unroll
    for (int s = 16; s > 0; s >>= 1) {
        hi = max(hi, __shfl_xor_sync(0xFFFFFFFFu, hi, s));
        lo = min(lo, __shfl_xor_sync(0xFFFFFFFFu, lo, s));
    }
    int wid = threadIdx.x >> 5;
    if ((threadIdx.x & 31) == 0) { slo[wid] = lo; shi[wid] = hi; }
    __syncthreads();
    if (threadIdx.x == 0) {
        lo = slo[0]; hi = shi[0];
#pragma unroll
        for (int i = 1; i < 8; i++) { lo = min(lo, slo[i]); hi = max(hi, shi[i]); }
        g_plo[blockIdx.x] = lo;
        g_phi[blockIdx.x] = hi;
    }
}

__global__ __launch_bounds__(NT) void lmorph_main_kernel(
    const float* __restrict__ in,
    const float* __restrict__ filt,
    const float* __restrict__ p,
    float* __restrict__ out)
{
    __shared__ u64t sx[C_][SH2][SWP];  // packed raw pairs (x[w], x[w+32])
    __shared__ u64t sf2[C_][K2_];      // packed broadcast: 1 + f - lo*inv
    __shared__ float sscal[2];         // lo, inv

    const int z = blockIdx.z;          // n*O_ + o
    const int n = z >> 2;
    const int o = z & 3;
    const int w0 = blockIdx.x * OWB;
    const int h0 = blockIdx.y * OHB;
    const int tid = threadIdx.x;
    const int tx = tid & 31;
    const int ty = tid >> 5;           // 0..3

    // Phase A: raw packed tile load (clamped cols/rows are safe fillers)
    for (int idx = tid; idx < C_ * SH2 * SWP; idx += NT) {
        int c   = idx / (SH2 * SWP);
        int rem = idx - c * (SH2 * SWP);
        int r   = rem / SWP;
        int q   = rem - r * SWP;
        int h  = min(h0 + r, H_ - 1);
        int wA = min(w0 + q, W_ - 1);
        int wB = min(w0 + q + 32, W_ - 1);
        const float* row = in + ((n * C_ + c) * H_ + h) * W_;
        sx[c][r][q] = pack2(row[wA], row[wB]);
    }

    // Phase B: warp 0 reduces the 128 min/max partials
    if (tid < 32) {
        unsigned lo = 0xFFFFFFFFu, hi = 0u;
#pragma unroll
        for (int i = 0; i < MMB / 32; i++) {
            lo = min(lo, g_plo[tid + 32 * i]);
            hi = max(hi, g_phi[tid + 32 * i]);
        }
#pragma unroll
        for (int s = 16; s > 0; s >>= 1) {
            lo = min(lo, __shfl_xor_sync(0xFFFFFFFFu, lo, s));
            hi = max(hi, __shfl_xor_sync(0xFFFFFFFFu, hi, s));
        }
        if (tid == 0) {
            float flo = key2f(lo), fhi = key2f(hi);
            sscal[0] = flo;
            sscal[1] = __fdividef(1.0f, fhi - flo);
        }
    }
    __syncthreads();

    const float lo  = sscal[0];
    const float inv = sscal[1];

    // Phase C: folded filters, packed broadcast: t = x*inv + (1 + f - lo*inv)
    if (tid < C_ * K2_) {
        int c = tid / K2_;
        int k = tid - c * K2_;
        float v = 1.0f + filt[(o * C_ + c) * K2_ + k] - lo * inv;
        sf2[c][k] = pack2(v, v);
    }

    // per-channel packed poly coeffs for 2^(pe*l), degree 3: Ck = Ak * pe^k
    const float A1 = 0.69314718f, A2 = 0.24022651f, A3 = 0.05550411f;
    u64t K1[C_], K2p[C_], K3[C_];
#pragma unroll
    for (int c = 0; c < C_; c++) {
        float pe  = p[o * C_ + c];
        float pe2 = pe * pe;
        float c1 = A1 * pe, c2 = A2 * pe2, c3 = A3 * pe2 * pe;
        K1[c] = pack2(c1, c1); K2p[c] = pack2(c2, c2); K3[c] = pack2(c3, c3);
    }
    __syncthreads();

    const int ow  = w0 + tx;
    const int ow2 = ow + 32;

    const u64t inv2 = pack2(inv, inv);
    const u64t ONE2 = pack2(1.0f, 1.0f);

    u64t num[4], den[4];
#pragma unroll
    for (int r = 0; r < 4; r++) { num[r] = 0ull; den[r] = 0ull; }

#pragma unroll
    for (int c = 0; c < C_; c++) {
        const u64t k1 = K1[c], k2 = K2p[c], k3 = K3[c];
#pragma unroll
        for (int i = 0; i < KH_; i++) {
#pragma unroll
            for (int j = 0; j < KW_; j++) {
                const int k = i * KW_ + j;
                const u64t f2k = sf2[c][k];
                u64t t0 = fma2_(sx[c][ty      + i][tx + j], inv2, f2k);
                u64t t1 = fma2_(sx[c][ty + 4  + i][tx + j], inv2, f2k);
                u64t t2 = fma2_(sx[c][ty + 8  + i][tx + j], inv2, f2k);
                u64t t3 = fma2_(sx[c][ty + 12 + i][tx + j], inv2, f2k);
                float2 f0 = unpack2(t0), f1 = unpack2(t1);
                float2 f2 = unpack2(t2), f3 = unpack2(t3);
                u64t l0 = pack2(fast_lg2(f0.x), fast_lg2(f0.y));
                u64t l1 = pack2(fast_lg2(f1.x), fast_lg2(f1.y));
                u64t l2 = pack2(fast_lg2(f2.x), fast_lg2(f2.y));
                u64t l3 = pack2(fast_lg2(f3.x), fast_lg2(f3.y));
                u64t u0 = fma2_(l0, k3, k2);
                u64t u1 = fma2_(l1, k3, k2);
                u64t u2 = fma2_(l2, k3, k2);
                u64t u3 = fma2_(l3, k3, k2);
                u0 = fma2_(l0, u0, k1);  u1 = fma2_(l1, u1, k1);
                u2 = fma2_(l2, u2, k1);  u3 = fma2_(l3, u3, k1);
                u64t w0p = fma2_(l0, u0, ONE2);
                u64t w1p = fma2_(l1, u1, ONE2);
                u64t w2p = fma2_(l2, u2, ONE2);
                u64t w3p = fma2_(l3, u3, ONE2);
                den[0] = add2_(den[0], w0p);  num[0] = fma2_(w0p, t0, num[0]);
                den[1] = add2_(den[1], w1p);  num[1] = fma2_(w1p, t1, num[1]);
                den[2] = add2_(den[2], w2p);  num[2] = fma2_(w2p, t2, num[2]);
                den[3] = add2_(den[3], w3p);  num[3] = fma2_(w3p, t3, num[3]);
            }
        }
    }

    float* obase = out + (n * O_ + o) * HO_ * WO_;
#pragma unroll
    for (int r = 0; r < 4; r++) {
        int oh = h0 + ty + 4 * r;
        if (oh < HO_) {
            float2 nf = unpack2(num[r]);
            float2 df = unpack2(den[r]);
            float* orow = obase + oh * WO_;
            orow[ow] = __fdividef(nf.x, df.x);
            if (ow2 < WO_) orow[ow2] = __fdividef(nf.y, df.y);
        }
    }
}

extern "C" void kernel_launch(void* const* d_in, const int* in_sizes, int n_in,
                              void* d_out, int out_size) {
    const float* in   = (const float*)d_in[0];   // [4,2,256,256]
    const float* filt = (const float*)d_in[1];   // [4,2,5,5]
    const float* p    = (const float*)d_in[2];   // [4,2]
    float* out = (float*)d_out;                  // [4,4,252,252]

    lmorph_minmax_kernel<<<MMB, 256>>>(in, (N_ * C_ * H_ * W_) / 4);

    dim3 block(NT);
    dim3 grid((WO_ + OWB - 1) / OWB, (HO_ + OHB - 1) / OHB, N_ * O_);
    lmorph_main_kernel<<<grid, block>>>(in, filt, p, out);
}

// round 9
// speedup vs baseline: 1.1752x; 1.0654x over previous
#include <cuda_runtime.h>

// LMorph: out[n,o,h,w] = sum_{c,ij} t^(p+1) / sum_{c,ij} t^p,
//   t = (1 + (in - gmin)/(gmax - gmin))[n,c,h+i,w+j] + filt[o,c,i,j]
// Shapes: in [4,2,256,256] f32, filt [4,2,5,5] f32, p [4,2] f32, out [4,4,252,252] f32.
// Each thread computes FOUR outputs: rows (oh, oh+8) x cols (ow, ow+32), packed f32x2.
// (R6 configuration — best measured — with a degree-3 poly for 2^(pe*l).)

#define N_  4
#define C_  2
#define O_  4
#define H_  256
#define W_  256
#define KH_ 5
#define KW_ 5
#define K2_ (KH_ * KW_)
#define HO_ 252
#define WO_ 252

#define TX 32
#define TY 8
#define NT (TX * TY)
#define OWB 64              // output columns per block (2 per thread)
#define OHB 16              // output rows per block (2 per thread: ty, ty+8)
#define SWP 36              // pair-columns in tile
#define SH2 (OHB + KH_ - 1) // 20 tile rows

#define MMB 256             // minmax partial blocks

typedef unsigned long long u64t;

__device__ __forceinline__ float fast_lg2(float x) {
    float r;
    asm("lg2.approx.f32 %0, %1;" : "=f"(r) : "f"(x));
    return r;
}
__device__ __forceinline__ u64t pack2(float a, float b) {
    u64t r; asm("mov.b64 %0, {%1, %2};" : "=l"(r) : "f"(a), "f"(b)); return r;
}
__device__ __forceinline__ float2 unpack2(u64t v) {
    float2 f; asm("mov.b64 {%0, %1}, %2;" : "=f"(f.x), "=f"(f.y) : "l"(v)); return f;
}
__device__ __forceinline__ u64t fma2_(u64t a, u64t b, u64t c) {
    u64t r; asm("fma.rn.f32x2 %0, %1, %2, %3;" : "=l"(r) : "l"(a), "l"(b), "l"(c)); return r;
}
__device__ __forceinline__ u64t add2_(u64t a, u64t b) {
    u64t r; asm("add.rn.f32x2 %0, %1, %2;" : "=l"(r) : "l"(a), "l"(b)); return r;
}

// ---- orderable-uint encoding for float min/max ----
__device__ __forceinline__ unsigned f2key(float f) {
    unsigned u = __float_as_uint(f);
    return (u & 0x80000000u) ? ~u : (u | 0x80000000u);
}
__device__ __forceinline__ float key2f(unsigned k) {
    unsigned u = (k & 0x80000000u) ? (k & 0x7FFFFFFFu) : ~k;
    return __uint_as_float(u);
}

// per-block partial min/max keys (no atomics, no init kernel)
__device__ unsigned g_plo[MMB];
__device__ unsigned g_phi[MMB];

__global__ __launch_bounds__(256) void lmorph_minmax_kernel(
    const float* __restrict__ in, int n4)
{
    __shared__ unsigned slo[8], shi[8];
    unsigned lo = 0xFFFFFFFFu, hi = 0u;
    const float4* in4 = (const float4*)in;
    for (int i = blockIdx.x * blockDim.x + threadIdx.x; i < n4;
         i += gridDim.x * blockDim.x) {
        float4 v = in4[i];
        unsigned kx = f2key(v.x), ky = f2key(v.y), kz = f2key(v.z), kw = f2key(v.w);
        hi = max(hi, max(max(kx, ky), max(kz, kw)));
        lo = min(lo, min(min(kx, ky), min(kz, kw)));
    }
#pragma unroll
    for (int s = 16; s > 0; s >>= 1) {
        hi = max(hi, __shfl_xor_sync(0xFFFFFFFFu, hi, s));
        lo = min(lo, __shfl_xor_sync(0xFFFFFFFFu, lo, s));
    }
    int wid = threadIdx.x >> 5;
    if ((threadIdx.x & 31) == 0) { slo[wid] = lo; shi[wid] = hi; }
    __syncthreads();
    if (threadIdx.x == 0) {
        lo = slo[0]; hi = shi[0];
#pragma unroll
        for (int i = 1; i < 8; i++) { lo = min(lo, slo[i]); hi = max(hi, shi[i]); }
        g_plo[blockIdx.x] = lo;
        g_phi[blockIdx.x] = hi;
    }
}

__global__ __launch_bounds__(NT) void lmorph_main_kernel(
    const float* __restrict__ in,
    const float* __restrict__ filt,
    const float* __restrict__ p,
    float* __restrict__ out)
{
    __shared__ u64t sx[C_][SH2][SWP];  // packed raw pairs (x[w], x[w+32])
    __shared__ u64t sf2[C_][K2_];      // packed broadcast: 1 + f - lo*inv
    __shared__ float sscal[2];         // lo, inv

    const int z = blockIdx.z;          // n*O_ + o
    const int n = z >> 2;
    const int o = z & 3;
    const int w0 = blockIdx.x * OWB;
    const int h0 = blockIdx.y * OHB;
    const int tid = threadIdx.x;
    const int tx = tid & 31;
    const int ty = tid >> 5;

    // Phase A: raw packed tile load (clamped cols/rows are safe fillers)
    for (int idx = tid; idx < C_ * SH2 * SWP; idx += NT) {
        int c   = idx / (SH2 * SWP);
        int rem = idx - c * (SH2 * SWP);
        int r   = rem / SWP;
        int q   = rem - r * SWP;
        int h  = min(h0 + r, H_ - 1);
        int wA = min(w0 + q, W_ - 1);
        int wB = min(w0 + q + 32, W_ - 1);
        const float* row = in + ((n * C_ + c) * H_ + h) * W_;
        sx[c][r][q] = pack2(row[wA], row[wB]);
    }

    // Phase B: warp 0 reduces the 256 min/max partials
    if (tid < 32) {
        unsigned lo = 0xFFFFFFFFu, hi = 0u;
#pragma unroll
        for (int i = 0; i < MMB / 32; i++) {
            lo = min(lo, g_plo[tid + 32 * i]);
            hi = max(hi, g_phi[tid + 32 * i]);
        }
#pragma unroll
        for (int s = 16; s > 0; s >>= 1) {
            lo = min(lo, __shfl_xor_sync(0xFFFFFFFFu, lo, s));
            hi = max(hi, __shfl_xor_sync(0xFFFFFFFFu, hi, s));
        }
        if (tid == 0) {
            float flo = key2f(lo), fhi = key2f(hi);
            sscal[0] = flo;
            sscal[1] = __fdividef(1.0f, fhi - flo);
        }
    }
    __syncthreads();

    const float lo  = sscal[0];
    const float inv = sscal[1];

    // Phase C: folded filters, packed broadcast: t = x*inv + (1 + f - lo*inv)
    if (tid < C_ * K2_) {
        int c = tid / K2_;
        int k = tid - c * K2_;
        float v = 1.0f + filt[(o * C_ + c) * K2_ + k] - lo * inv;
        sf2[c][k] = pack2(v, v);
    }

    // per-channel packed poly coeffs for 2^(pe*l), degree 3: Ck = Ak * pe^k
    const float A1 = 0.69314718f, A2 = 0.24022651f, A3 = 0.05550411f;
    u64t K1[C_], K2p[C_], K3[C_];
#pragma unroll
    for (int c = 0; c < C_; c++) {
        float pe  = p[o * C_ + c];
        float pe2 = pe * pe;
        float c1 = A1 * pe, c2 = A2 * pe2, c3 = A3 * pe2 * pe;
        K1[c] = pack2(c1, c1); K2p[c] = pack2(c2, c2); K3[c] = pack2(c3, c3);
    }
    __syncthreads();

    const int ohA = h0 + ty;           // always < 252 (h0<=240, ty<=7)
    const int ohB = ohA + TY;          // may exceed 251 -> store-guarded
    const int ow  = w0 + tx;
    const int ow2 = ow + 32;

    const u64t inv2 = pack2(inv, inv);
    const u64t ONE2 = pack2(1.0f, 1.0f);
    u64t numA = 0ull, denA = 0ull, numB = 0ull, denB = 0ull;

#pragma unroll
    for (int c = 0; c < C_; c++) {
        const u64t k1 = K1[c], k2 = K2p[c], k3 = K3[c];
#pragma unroll
        for (int i = 0; i < KH_; i++) {
#pragma unroll
            for (int j = 0; j < KW_; j++) {
                const int k = i * KW_ + j;
                const u64t f2k = sf2[c][k];
                u64t ta = fma2_(sx[c][ty + i][tx + j], inv2, f2k);
                u64t tb = fma2_(sx[c][ty + TY + i][tx + j], inv2, f2k);
                float2 fa = unpack2(ta);
                float2 fb = unpack2(tb);
                u64t la = pack2(fast_lg2(fa.x), fast_lg2(fa.y));
                u64t lb = pack2(fast_lg2(fb.x), fast_lg2(fb.y));
                u64t ua = fma2_(la, k3, k2);
                u64t ub = fma2_(lb, k3, k2);
                ua = fma2_(la, ua, k1);
                ub = fma2_(lb, ub, k1);
                u64t wa = fma2_(la, ua, ONE2);
                u64t wb = fma2_(lb, ub, ONE2);
                denA = add2_(denA, wa);
                denB = add2_(denB, wb);
                numA = fma2_(wa, ta, numA);
                numB = fma2_(wb, tb, numB);
            }
        }
    }
    float2 na = unpack2(numA), da = unpack2(denA);
    float2 nb = unpack2(numB), db = unpack2(denB);
    float* obase = out + (n * O_ + o) * HO_ * WO_;
    {
        float* orow = obase + ohA * WO_;
        orow[ow] = __fdividef(na.x, da.x);
        if (ow2 < WO_) orow[ow2] = __fdividef(na.y, da.y);
    }
    if (ohB < HO_) {
        float* orow = obase + ohB * WO_;
        orow[ow] = __fdividef(nb.x, db.x);
        if (ow2 < WO_) orow[ow2] = __fdividef(nb.y, db.y);
    }
}

extern "C" void kernel_launch(void* const* d_in, const int* in_sizes, int n_in,
                              void* d_out, int out_size) {
    const float* in   = (const float*)d_in[0];   // [4,2,256,256]
    const float* filt = (const float*)d_in[1];   // [4,2,5,5]
    const float* p    = (const float*)d_in[2];   // [4,2]
    float* out = (float*)d_out;                  // [4,4,252,252]

    lmorph_minmax_kernel<<<MMB, 256>>>(in, (N_ * C_ * H_ * W_) / 4);

    dim3 block(NT);
    dim3 grid((WO_ + OWB - 1) / OWB, (HO_ + OHB - 1) / OHB, N_ * O_);
    lmorph_main_kernel<<<grid, block>>>(in, filt, p, out);
}

// round 10
// speedup vs baseline: 1.2832x; 1.0918x over previous
#include <cuda_runtime.h>

// LMorph: out[n,o,h,w] = sum_{c,ij} t^(p+1) / sum_{c,ij} t^p,
//   t = (1 + (in - gmin)/(gmax - gmin))[n,c,h+i,w+j] + filt[o,c,i,j]
// Shapes: in [4,2,256,256] f32, filt [4,2,5,5] f32, p [4,2] f32, out [4,4,252,252] f32.
// Each thread computes FOUR outputs: rows (oh, oh+8) x cols (ow, ow+32), packed f32x2.
// (R9 configuration with a degree-2 poly for 2^(pe*l).)

#define N_  4
#define C_  2
#define O_  4
#define H_  256
#define W_  256
#define KH_ 5
#define KW_ 5
#define K2_ (KH_ * KW_)
#define HO_ 252
#define WO_ 252

#define TX 32
#define TY 8
#define NT (TX * TY)
#define OWB 64              // output columns per block (2 per thread)
#define OHB 16              // output rows per block (2 per thread: ty, ty+8)
#define SWP 36              // pair-columns in tile
#define SH2 (OHB + KH_ - 1) // 20 tile rows

#define MMB 256             // minmax partial blocks

typedef unsigned long long u64t;

__device__ __forceinline__ float fast_lg2(float x) {
    float r;
    asm("lg2.approx.f32 %0, %1;" : "=f"(r) : "f"(x));
    return r;
}
__device__ __forceinline__ u64t pack2(float a, float b) {
    u64t r; asm("mov.b64 %0, {%1, %2};" : "=l"(r) : "f"(a), "f"(b)); return r;
}
__device__ __forceinline__ float2 unpack2(u64t v) {
    float2 f; asm("mov.b64 {%0, %1}, %2;" : "=f"(f.x), "=f"(f.y) : "l"(v)); return f;
}
__device__ __forceinline__ u64t fma2_(u64t a, u64t b, u64t c) {
    u64t r; asm("fma.rn.f32x2 %0, %1, %2, %3;" : "=l"(r) : "l"(a), "l"(b), "l"(c)); return r;
}
__device__ __forceinline__ u64t add2_(u64t a, u64t b) {
    u64t r; asm("add.rn.f32x2 %0, %1, %2;" : "=l"(r) : "l"(a), "l"(b)); return r;
}

// ---- orderable-uint encoding for float min/max ----
__device__ __forceinline__ unsigned f2key(float f) {
    unsigned u = __float_as_uint(f);
    return (u & 0x80000000u) ? ~u : (u | 0x80000000u);
}
__device__ __forceinline__ float key2f(unsigned k) {
    unsigned u = (k & 0x80000000u) ? (k & 0x7FFFFFFFu) : ~k;
    return __uint_as_float(u);
}

// per-block partial min/max keys (no atomics, no init kernel)
__device__ unsigned g_plo[MMB];
__device__ unsigned g_phi[MMB];

__global__ __launch_bounds__(256) void lmorph_minmax_kernel(
    const float* __restrict__ in, int n4)
{
    __shared__ unsigned slo[8], shi[8];
    unsigned lo = 0xFFFFFFFFu, hi = 0u;
    const float4* in4 = (const float4*)in;
    for (int i = blockIdx.x * blockDim.x + threadIdx.x; i < n4;
         i += gridDim.x * blockDim.x) {
        float4 v = in4[i];
        unsigned kx = f2key(v.x), ky = f2key(v.y), kz = f2key(v.z), kw = f2key(v.w);
        hi = max(hi, max(max(kx, ky), max(kz, kw)));
        lo = min(lo, min(min(kx, ky), min(kz, kw)));
    }
#pragma unroll
    for (int s = 16; s > 0; s >>= 1) {
        hi = max(hi, __shfl_xor_sync(0xFFFFFFFFu, hi, s));
        lo = min(lo, __shfl_xor_sync(0xFFFFFFFFu, lo, s));
    }
    int wid = threadIdx.x >> 5;
    if ((threadIdx.x & 31) == 0) { slo[wid] = lo; shi[wid] = hi; }
    __syncthreads();
    if (threadIdx.x == 0) {
        lo = slo[0]; hi = shi[0];
#pragma unroll
        for (int i = 1; i < 8; i++) { lo = min(lo, slo[i]); hi = max(hi, shi[i]); }
        g_plo[blockIdx.x] = lo;
        g_phi[blockIdx.x] = hi;
    }
}

__global__ __launch_bounds__(NT) void lmorph_main_kernel(
    const float* __restrict__ in,
    const float* __restrict__ filt,
    const float* __restrict__ p,
    float* __restrict__ out)
{
    __shared__ u64t sx[C_][SH2][SWP];  // packed raw pairs (x[w], x[w+32])
    __shared__ u64t sf2[C_][K2_];      // packed broadcast: 1 + f - lo*inv
    __shared__ float sscal[2];         // lo, inv

    const int z = blockIdx.z;          // n*O_ + o
    const int n = z >> 2;
    const int o = z & 3;
    const int w0 = blockIdx.x * OWB;
    const int h0 = blockIdx.y * OHB;
    const int tid = threadIdx.x;
    const int tx = tid & 31;
    const int ty = tid >> 5;

    // Phase A: raw packed tile load (clamped cols/rows are safe fillers)
    for (int idx = tid; idx < C_ * SH2 * SWP; idx += NT) {
        int c   = idx / (SH2 * SWP);
        int rem = idx - c * (SH2 * SWP);
        int r   = rem / SWP;
        int q   = rem - r * SWP;
        int h  = min(h0 + r, H_ - 1);
        int wA = min(w0 + q, W_ - 1);
        int wB = min(w0 + q + 32, W_ - 1);
        const float* row = in + ((n * C_ + c) * H_ + h) * W_;
        sx[c][r][q] = pack2(row[wA], row[wB]);
    }

    // Phase B: warp 0 reduces the 256 min/max partials
    if (tid < 32) {
        unsigned lo = 0xFFFFFFFFu, hi = 0u;
#pragma unroll
        for (int i = 0; i < MMB / 32; i++) {
            lo = min(lo, g_plo[tid + 32 * i]);
            hi = max(hi, g_phi[tid + 32 * i]);
        }
#pragma unroll
        for (int s = 16; s > 0; s >>= 1) {
            lo = min(lo, __shfl_xor_sync(0xFFFFFFFFu, lo, s));
            hi = max(hi, __shfl_xor_sync(0xFFFFFFFFu, hi, s));
        }
        if (tid == 0) {
            float flo = key2f(lo), fhi = key2f(hi);
            sscal[0] = flo;
            sscal[1] = __fdividef(1.0f, fhi - flo);
        }
    }
    __syncthreads();

    const float lo  = sscal[0];
    const float inv = sscal[1];

    // Phase C: folded filters, packed broadcast: t = x*inv + (1 + f - lo*inv)
    if (tid < C_ * K2_) {
        int c = tid / K2_;
        int k = tid - c * K2_;
        float v = 1.0f + filt[(o * C_ + c) * K2_ + k] - lo * inv;
        sf2[c][k] = pack2(v, v);
    }

    // per-channel packed poly coeffs for 2^(pe*l), degree 2: Ck = Ak * pe^k
    const float A1 = 0.69314718f, A2 = 0.24022651f;
    u64t K1[C_], K2p[C_];
#pragma unroll
    for (int c = 0; c < C_; c++) {
        float pe  = p[o * C_ + c];
        float c1 = A1 * pe, c2 = A2 * pe * pe;
        K1[c] = pack2(c1, c1); K2p[c] = pack2(c2, c2);
    }
    __syncthreads();

    const int ohA = h0 + ty;           // always < 252 (h0<=240, ty<=7)
    const int ohB = ohA + TY;          // may exceed 251 -> store-guarded
    const int ow  = w0 + tx;
    const int ow2 = ow + 32;

    const u64t inv2 = pack2(inv, inv);
    const u64t ONE2 = pack2(1.0f, 1.0f);
    u64t numA = 0ull, denA = 0ull, numB = 0ull, denB = 0ull;

#pragma unroll
    for (int c = 0; c < C_; c++) {
        const u64t k1 = K1[c], k2 = K2p[c];
#pragma unroll
        for (int i = 0; i < KH_; i++) {
#pragma unroll
            for (int j = 0; j < KW_; j++) {
                const int k = i * KW_ + j;
                const u64t f2k = sf2[c][k];
                u64t ta = fma2_(sx[c][ty + i][tx + j], inv2, f2k);
                u64t tb = fma2_(sx[c][ty + TY + i][tx + j], inv2, f2k);
                float2 fa = unpack2(ta);
                float2 fb = unpack2(tb);
                u64t la = pack2(fast_lg2(fa.x), fast_lg2(fa.y));
                u64t lb = pack2(fast_lg2(fb.x), fast_lg2(fb.y));
                u64t ua = fma2_(la, k2, k1);
                u64t ub = fma2_(lb, k2, k1);
                u64t wa = fma2_(la, ua, ONE2);
                u64t wb = fma2_(lb, ub, ONE2);
                denA = add2_(denA, wa);
                denB = add2_(denB, wb);
                numA = fma2_(wa, ta, numA);
                numB = fma2_(wb, tb, numB);
            }
        }
    }
    float2 na = unpack2(numA), da = unpack2(denA);
    float2 nb = unpack2(numB), db = unpack2(denB);
    float* obase = out + (n * O_ + o) * HO_ * WO_;
    {
        float* orow = obase + ohA * WO_;
        orow[ow] = __fdividef(na.x, da.x);
        if (ow2 < WO_) orow[ow2] = __fdividef(na.y, da.y);
    }
    if (ohB < HO_) {
        float* orow = obase + ohB * WO_;
        orow[ow] = __fdividef(nb.x, db.x);
        if (ow2 < WO_) orow[ow2] = __fdividef(nb.y, db.y);
    }
}

extern "C" void kernel_launch(void* const* d_in, const int* in_sizes, int n_in,
                              void* d_out, int out_size) {
    const float* in   = (const float*)d_in[0];   // [4,2,256,256]
    const float* filt = (const float*)d_in[1];   // [4,2,5,5]
    const float* p    = (const float*)d_in[2];   // [4,2]
    float* out = (float*)d_out;                  // [4,4,252,252]

    lmorph_minmax_kernel<<<MMB, 256>>>(in, (N_ * C_ * H_ * W_) / 4);

    dim3 block(NT);
    dim3 grid((WO_ + OWB - 1) / OWB, (HO_ + OHB - 1) / OHB, N_ * O_);
    lmorph_main_kernel<<<grid, block>>>(in, filt, p, out);
}